// round 3
// baseline (speedup 1.0000x reference)
#include <cuda_runtime.h>
#include <cstdint>

// Problem constants (fixed by the dataset)
#define NN   50000
#define EE   800000
#define NF   256
#define NH   128
#define NO   64
#define NB   ((NN + 255) / 256)   // 196 scan blocks

// ---------------- scratch (no allocations allowed) ----------------
__device__ int   g_deg[NN];
__device__ int   g_cursor[NN];
__device__ float g_dis[NN];
__device__ int   g_off[NN + 1];
__device__ int   g_bsum[NB];
__device__ int   g_bbase[NB];
__device__ int   g_csr_src[EE];
__device__ float g_csr_norm[EE];
__device__ float g_h1[(size_t)NN * NH];   // x @ W1
__device__ float g_hr[(size_t)NN * NH];   // relu(agg1 + b1)
__device__ float g_h2[(size_t)NN * NO];   // hr @ W2

// ---------------- packed f32x2 helpers ----------------
__device__ __forceinline__ unsigned long long pack2(float lo, float hi) {
    unsigned long long r;
    asm("mov.b64 %0, {%1, %2};" : "=l"(r) : "f"(lo), "f"(hi));
    return r;
}
__device__ __forceinline__ void unpack2(unsigned long long v, float& lo, float& hi) {
    asm("mov.b64 {%0, %1}, %2;" : "=f"(lo), "=f"(hi) : "l"(v));
}
__device__ __forceinline__ unsigned long long fma2(unsigned long long a,
                                                   unsigned long long b,
                                                   unsigned long long c) {
    unsigned long long d;
    asm("fma.rn.f32x2 %0, %1, %2, %3;" : "=l"(d) : "l"(a), "l"(b), "l"(c));
    return d;
}

// ---------------- small graph-prep kernels ----------------
__global__ void k_zero_deg() {
    int i = blockIdx.x * blockDim.x + threadIdx.x;
    if (i < NN) g_deg[i] = 0;
}

// edge_index is int32 (JAX default config downcasts int64 -> int32)
__global__ void k_hist(const int* __restrict__ ei, int E, int n) {
    int e = blockIdx.x * blockDim.x + threadIdx.x;
    if (e < E) {
        int d = ei[E + e];   // dst row
        if ((unsigned)d < (unsigned)n) atomicAdd(&g_deg[d], 1);
    }
}

__global__ void k_blocksum(int n) {
    __shared__ int sh[256];
    int i = blockIdx.x * 256 + threadIdx.x;
    sh[threadIdx.x] = (i < n) ? g_deg[i] : 0;
    __syncthreads();
    for (int s = 128; s > 0; s >>= 1) {
        if (threadIdx.x < s) sh[threadIdx.x] += sh[threadIdx.x + s];
        __syncthreads();
    }
    if (threadIdx.x == 0) g_bsum[blockIdx.x] = sh[0];
}

__global__ void k_scan_bases(int nb) {
    if (threadIdx.x == 0 && blockIdx.x == 0) {
        int s = 0;
        for (int i = 0; i < nb; i++) { int t = g_bsum[i]; g_bbase[i] = s; s += t; }
    }
}

__global__ void k_offsets(int n) {
    __shared__ int sh[256];
    int tid = threadIdx.x;
    int i = blockIdx.x * 256 + tid;
    int v = (i < n) ? g_deg[i] : 0;
    sh[tid] = v;
    __syncthreads();
    // inclusive Hillis-Steele scan
    for (int ofs = 1; ofs < 256; ofs <<= 1) {
        int t = (tid >= ofs) ? sh[tid - ofs] : 0;
        __syncthreads();
        sh[tid] += t;
        __syncthreads();
    }
    if (i < n) {
        int base = g_bbase[blockIdx.x];
        g_off[i] = base + sh[tid] - v;                 // exclusive
        g_dis[i] = (v > 0) ? rsqrtf((float)v) : 0.0f;
        g_cursor[i] = 0;
        if (i == n - 1) g_off[n] = base + sh[tid];
    }
}

__global__ void k_fill(const int* __restrict__ ei, int E, int n) {
    int e = blockIdx.x * blockDim.x + threadIdx.x;
    if (e < E) {
        int s = ei[e];
        int d = ei[E + e];
        if ((unsigned)s < (unsigned)n && (unsigned)d < (unsigned)n) {
            int pos = g_off[d] + atomicAdd(&g_cursor[d], 1);
            g_csr_src[pos]  = s;
            g_csr_norm[pos] = g_dis[s] * g_dis[d];
        }
    }
}

// ---------------- register-tiled SGEMM body with packed fma.f32x2 ----------------
// C[M,N] = A[M,K] @ B[K,N], row-major, K % BK == 0, N == BN.
template <int BM, int BN, int BK, int TM, int TN>
__device__ __forceinline__ void gemm_body(const float* __restrict__ A,
                                          const float* __restrict__ B,
                                          float* __restrict__ C,
                                          int M, int N, int K) {
    constexpr int NTH = (BM / TM) * (BN / TN);
    __shared__ __align__(16) float As[BK][BM];   // transposed tile
    __shared__ __align__(16) float Bs[BK][BN];

    const int tid = threadIdx.x;
    const int blockRow = blockIdx.x;
    const int tCol = tid % (BN / TN);
    const int tRow = tid / (BN / TN);

    unsigned long long acc[TM][TN / 2];
#pragma unroll
    for (int i = 0; i < TM; i++)
#pragma unroll
        for (int j = 0; j < TN / 2; j++) acc[i][j] = 0ull;

    for (int k0 = 0; k0 < K; k0 += BK) {
        // load A tile (BM x BK), store transposed
#pragma unroll
        for (int i = tid; i < BM * BK / 4; i += NTH) {
            int r = i / (BK / 4);
            int kv = i % (BK / 4);
            int gr = blockRow * BM + r;
            float4 v = make_float4(0.f, 0.f, 0.f, 0.f);
            if (gr < M) v = *(const float4*)(A + (size_t)gr * K + k0 + kv * 4);
            As[kv * 4 + 0][r] = v.x;
            As[kv * 4 + 1][r] = v.y;
            As[kv * 4 + 2][r] = v.z;
            As[kv * 4 + 3][r] = v.w;
        }
        // load B tile (BK x BN)
#pragma unroll
        for (int i = tid; i < BK * BN / 4; i += NTH) {
            int r = i / (BN / 4);
            int cv = i % (BN / 4);
            *(float4*)&Bs[r][cv * 4] = *(const float4*)(B + (size_t)(k0 + r) * N + cv * 4);
        }
        __syncthreads();

#pragma unroll
        for (int kk = 0; kk < BK; kk++) {
            unsigned long long m2[TM];
#pragma unroll
            for (int i = 0; i < TM; i++) {
                float m = As[kk][tRow * TM + i];
                m2[i] = pack2(m, m);
            }
            unsigned long long b2r[TN / 2];
#pragma unroll
            for (int j = 0; j < TN / 2; j++)
                b2r[j] = *(const unsigned long long*)&Bs[kk][tCol * TN + 2 * j];
#pragma unroll
            for (int i = 0; i < TM; i++)
#pragma unroll
                for (int j = 0; j < TN / 2; j++)
                    acc[i][j] = fma2(m2[i], b2r[j], acc[i][j]);
        }
        __syncthreads();
    }

    // store
#pragma unroll
    for (int i = 0; i < TM; i++) {
        int gr = blockRow * BM + tRow * TM + i;
        if (gr >= M) continue;
#pragma unroll
        for (int j = 0; j < TN / 2; j += 2) {
            float a0, a1, a2, a3;
            unpack2(acc[i][j], a0, a1);
            unpack2(acc[i][j + 1], a2, a3);
            *(float4*)(C + (size_t)gr * N + tCol * TN + 2 * j) = make_float4(a0, a1, a2, a3);
        }
    }
}

// ---------------- gather-based SpMM body (CSR rows = dst) ----------------
// OUT[row,:] = act( sum_e norm_e * H[src_e,:] + bias )
template <int F, int RPW, bool RELU>
__device__ __forceinline__ void spmm_body(const float* __restrict__ H,
                                          const float* __restrict__ bias,
                                          float* __restrict__ OUT, int n) {
    constexpr int LANES = 32 / RPW;      // F == LANES * 4
    const int wpb  = blockDim.x / 32;
    const int gw   = blockIdx.x * wpb + (threadIdx.x >> 5);
    const int lane = threadIdx.x & 31;
    const int sub  = lane / LANES;
    const int li   = lane % LANES;
    const int row  = gw * RPW + sub;
    if (row >= n) return;

    const int s = g_off[row];
    const int e = g_off[row + 1];
    float4 acc = make_float4(0.f, 0.f, 0.f, 0.f);
    for (int p = s; p < e; p++) {
        int   src = g_csr_src[p];
        float nm  = g_csr_norm[p];
        float4 h = *(const float4*)(H + (size_t)src * F + li * 4);
        acc.x = fmaf(nm, h.x, acc.x);
        acc.y = fmaf(nm, h.y, acc.y);
        acc.z = fmaf(nm, h.z, acc.z);
        acc.w = fmaf(nm, h.w, acc.w);
    }
    float4 b = *(const float4*)(bias + li * 4);
    acc.x += b.x; acc.y += b.y; acc.z += b.z; acc.w += b.w;
    if (RELU) {
        acc.x = fmaxf(acc.x, 0.f);
        acc.y = fmaxf(acc.y, 0.f);
        acc.z = fmaxf(acc.z, 0.f);
        acc.w = fmaxf(acc.w, 0.f);
    }
    *(float4*)(OUT + (size_t)row * F + li * 4) = acc;
}

// ---------------- thin wrappers binding __device__ globals ----------------
__global__ void k_gemm1(const float* __restrict__ x, const float* __restrict__ W1, int n) {
    gemm_body<128, 128, 16, 8, 8>(x, W1, g_h1, n, NH, NF);
}
__global__ void k_spmm1(const float* __restrict__ b1, int n) {
    spmm_body<NH, 1, true>(g_h1, b1, g_hr, n);
}
__global__ void k_gemm2(const float* __restrict__ W2, int n) {
    gemm_body<128, 64, 16, 8, 8>(g_hr, W2, g_h2, n, NO, NH);
}
__global__ void k_spmm2(const float* __restrict__ b2, float* __restrict__ out, int n) {
    spmm_body<NO, 2, false>(g_h2, b2, out, n);
}

// ---------------- launcher ----------------
extern "C" void kernel_launch(void* const* d_in, const int* in_sizes, int n_in,
                              void* d_out, int out_size) {
    const float* x  = (const float*)d_in[0];
    const int*   ei = (const int*)d_in[1];     // int32 edge_index [2, E]
    const float* W1 = (const float*)d_in[2];
    const float* b1 = (const float*)d_in[3];
    const float* W2 = (const float*)d_in[4];
    const float* b2 = (const float*)d_in[5];
    float* out = (float*)d_out;

    const int n = in_sizes[0] / NF;   // 50000
    const int E = in_sizes[1] / 2;    // 800000
    const int nb = (n + 255) / 256;

    // graph prep
    k_zero_deg<<<(n + 255) / 256, 256>>>();
    k_hist<<<(E + 255) / 256, 256>>>(ei, E, n);
    k_blocksum<<<nb, 256>>>(n);
    k_scan_bases<<<1, 32>>>(nb);
    k_offsets<<<nb, 256>>>(n);
    k_fill<<<(E + 255) / 256, 256>>>(ei, E, n);

    // layer 1: h1 = x @ W1 ; hr = relu(Ahat @ h1 + b1)
    k_gemm1<<<(n + 127) / 128, 256>>>(x, W1, n);
    k_spmm1<<<(n + 7) / 8, 256>>>(b1, n);
    // layer 2: h2 = hr @ W2 ; out = Ahat @ h2 + b2
    k_gemm2<<<(n + 127) / 128, 128>>>(W2, n);
    k_spmm2<<<(n / 2 + 7) / 8, 256>>>(b2, out, n);
}

// round 5
// speedup vs baseline: 1.1378x; 1.1378x over previous
#include <cuda_runtime.h>
#include <cstdint>

// Problem constants (fixed by the dataset)
#define NN   50000
#define EE   800000
#define NF   256
#define NH   128
#define NO   64
#define NB   ((NN + 255) / 256)   // 196 scan blocks

// ---------------- scratch (no allocations allowed) ----------------
__device__ int   g_deg[NN];
__device__ int   g_cursor[NN];
__device__ float g_dis[NN];
__device__ int   g_off[NN + 1];
__device__ int   g_bsum[NB];
__device__ int   g_bbase[NB];
__device__ int   g_csr_src[EE];
__device__ float g_csr_norm[EE];
__device__ float g_h1[(size_t)NN * NH];   // x @ W1
__device__ float g_hr[(size_t)NN * NH];   // relu(agg1 + b1)
__device__ float g_h2[(size_t)NN * NO];   // hr @ W2

// ---------------- packed f32x2 helpers ----------------
__device__ __forceinline__ unsigned long long pack2(float lo, float hi) {
    unsigned long long r;
    asm("mov.b64 %0, {%1, %2};" : "=l"(r) : "f"(lo), "f"(hi));
    return r;
}
__device__ __forceinline__ void unpack2(unsigned long long v, float& lo, float& hi) {
    asm("mov.b64 {%0, %1}, %2;" : "=f"(lo), "=f"(hi) : "l"(v));
}
__device__ __forceinline__ unsigned long long fma2(unsigned long long a,
                                                   unsigned long long b,
                                                   unsigned long long c) {
    unsigned long long d;
    asm("fma.rn.f32x2 %0, %1, %2, %3;" : "=l"(d) : "l"(a), "l"(b), "l"(c));
    return d;
}

// ---------------- small graph-prep kernels ----------------
__global__ void k_zero_deg() {
    int i = blockIdx.x * blockDim.x + threadIdx.x;
    if (i < NN) g_deg[i] = 0;
}

// edge_index is int32
__global__ void k_hist(const int* __restrict__ ei, int E, int n) {
    int e = blockIdx.x * blockDim.x + threadIdx.x;
    if (e < E) {
        int d = ei[E + e];
        if ((unsigned)d < (unsigned)n) atomicAdd(&g_deg[d], 1);
    }
}

__global__ void k_blocksum(int n) {
    __shared__ int sh[256];
    int i = blockIdx.x * 256 + threadIdx.x;
    sh[threadIdx.x] = (i < n) ? g_deg[i] : 0;
    __syncthreads();
    for (int s = 128; s > 0; s >>= 1) {
        if (threadIdx.x < s) sh[threadIdx.x] += sh[threadIdx.x + s];
        __syncthreads();
    }
    if (threadIdx.x == 0) g_bsum[blockIdx.x] = sh[0];
}

// parallel exclusive scan of block sums (nb <= 256), single block
__global__ void k_scan_bases(int nb) {
    __shared__ int sh[256];
    int t = threadIdx.x;
    int v = (t < nb) ? g_bsum[t] : 0;
    sh[t] = v;
    __syncthreads();
    for (int o = 1; o < 256; o <<= 1) {
        int u = (t >= o) ? sh[t - o] : 0;
        __syncthreads();
        sh[t] += u;
        __syncthreads();
    }
    if (t < nb) g_bbase[t] = sh[t] - v;   // exclusive
}

__global__ void k_offsets(int n) {
    __shared__ int sh[256];
    int tid = threadIdx.x;
    int i = blockIdx.x * 256 + tid;
    int v = (i < n) ? g_deg[i] : 0;
    sh[tid] = v;
    __syncthreads();
    for (int ofs = 1; ofs < 256; ofs <<= 1) {
        int t = (tid >= ofs) ? sh[tid - ofs] : 0;
        __syncthreads();
        sh[tid] += t;
        __syncthreads();
    }
    if (i < n) {
        int base = g_bbase[blockIdx.x];
        g_off[i] = base + sh[tid] - v;
        g_dis[i] = (v > 0) ? rsqrtf((float)v) : 0.0f;
        g_cursor[i] = 0;
        if (i == n - 1) g_off[n] = base + sh[tid];
    }
}

__global__ void k_fill(const int* __restrict__ ei, int E, int n) {
    int e = blockIdx.x * blockDim.x + threadIdx.x;
    if (e < E) {
        int s = ei[e];
        int d = ei[E + e];
        if ((unsigned)s < (unsigned)n && (unsigned)d < (unsigned)n) {
            int pos = g_off[d] + atomicAdd(&g_cursor[d], 1);
            g_csr_src[pos]  = s;
            g_csr_norm[pos] = g_dis[s] * g_dis[d];
        }
    }
}

// ---------------- double-buffered register-tiled SGEMM (fma.f32x2) -------------
// C[M,N] = A[M,K] @ B[K,N], row-major, K % BK == 0, N == BN.
template <int BM, int BN, int BK, int TM, int TN>
__device__ __forceinline__ void gemm_body(const float* __restrict__ A,
                                          const float* __restrict__ B,
                                          float* __restrict__ C,
                                          int M, int N, int K) {
    constexpr int NTH = (BM / TM) * (BN / TN);
    constexpr int LA = BM * BK / (4 * NTH);   // float4 A loads per thread
    constexpr int LB = BK * BN / (4 * NTH);   // float4 B loads per thread
    __shared__ __align__(16) float As[2][BK][BM];   // transposed
    __shared__ __align__(16) float Bs[2][BK][BN];

    const int tid = threadIdx.x;
    const int blockRow = blockIdx.x;
    const int tCol = tid % (BN / TN);
    const int tRow = tid / (BN / TN);

    float4 ra[LA], rb[LB];

    // stage tile k0 into registers
    auto ldg_tile = [&](int k0) {
#pragma unroll
        for (int t = 0; t < LA; t++) {
            int i = tid + t * NTH;
            int r = i / (BK / 4);
            int kv = i % (BK / 4);
            int gr = blockRow * BM + r;
            ra[t] = (gr < M) ? *(const float4*)(A + (size_t)gr * K + k0 + kv * 4)
                             : make_float4(0.f, 0.f, 0.f, 0.f);
        }
#pragma unroll
        for (int t = 0; t < LB; t++) {
            int i = tid + t * NTH;
            int r = i / (BN / 4);
            int cv = i % (BN / 4);
            rb[t] = *(const float4*)(B + (size_t)(k0 + r) * N + cv * 4);
        }
    };
    // registers -> smem buffer
    auto sts_tile = [&](int buf) {
#pragma unroll
        for (int t = 0; t < LA; t++) {
            int i = tid + t * NTH;
            int r = i / (BK / 4);
            int kv = i % (BK / 4);
            As[buf][kv * 4 + 0][r] = ra[t].x;
            As[buf][kv * 4 + 1][r] = ra[t].y;
            As[buf][kv * 4 + 2][r] = ra[t].z;
            As[buf][kv * 4 + 3][r] = ra[t].w;
        }
#pragma unroll
        for (int t = 0; t < LB; t++) {
            int i = tid + t * NTH;
            int r = i / (BN / 4);
            int cv = i % (BN / 4);
            *(float4*)&Bs[buf][r][cv * 4] = rb[t];
        }
    };

    unsigned long long acc[TM][TN / 2];
#pragma unroll
    for (int i = 0; i < TM; i++)
#pragma unroll
        for (int j = 0; j < TN / 2; j++) acc[i][j] = 0ull;

    const int nk = K / BK;
    ldg_tile(0);
    sts_tile(0);
    __syncthreads();

    for (int kb = 0; kb < nk; kb++) {
        const int cur = kb & 1;
        if (kb + 1 < nk) ldg_tile((kb + 1) * BK);   // overlap with compute below

#pragma unroll
        for (int kk = 0; kk < BK; kk++) {
            float4 a0 = *(const float4*)&As[cur][kk][tRow * TM];
            float4 a1 = *(const float4*)&As[cur][kk][tRow * TM + 4];
            unsigned long long m2[TM];
            m2[0] = pack2(a0.x, a0.x); m2[1] = pack2(a0.y, a0.y);
            m2[2] = pack2(a0.z, a0.z); m2[3] = pack2(a0.w, a0.w);
            m2[4] = pack2(a1.x, a1.x); m2[5] = pack2(a1.y, a1.y);
            m2[6] = pack2(a1.z, a1.z); m2[7] = pack2(a1.w, a1.w);
            unsigned long long b2r[TN / 2];
            const unsigned long long* bp =
                (const unsigned long long*)&Bs[cur][kk][tCol * TN];
#pragma unroll
            for (int j = 0; j < TN / 2; j++) b2r[j] = bp[j];
#pragma unroll
            for (int i = 0; i < TM; i++)
#pragma unroll
                for (int j = 0; j < TN / 2; j++)
                    acc[i][j] = fma2(m2[i], b2r[j], acc[i][j]);
        }

        if (kb + 1 < nk) {
            __syncthreads();
            sts_tile(cur ^ 1);
            __syncthreads();
        }
    }

    // store
#pragma unroll
    for (int i = 0; i < TM; i++) {
        int gr = blockRow * BM + tRow * TM + i;
        if (gr >= M) continue;
#pragma unroll
        for (int j = 0; j < TN / 2; j += 2) {
            float a0, a1, a2, a3;
            unpack2(acc[i][j], a0, a1);
            unpack2(acc[i][j + 1], a2, a3);
            *(float4*)(C + (size_t)gr * N + tCol * TN + 2 * j) = make_float4(a0, a1, a2, a3);
        }
    }
}

// ---------------- gather-based SpMM body (CSR rows = dst) ----------------
template <int F, int RPW, bool RELU>
__device__ __forceinline__ void spmm_body(const float* __restrict__ H,
                                          const float* __restrict__ bias,
                                          float* __restrict__ OUT, int n) {
    constexpr int LANES = 32 / RPW;      // F == LANES * 4
    const int gw   = blockIdx.x * (blockDim.x / 32) + (threadIdx.x >> 5);
    const int lane = threadIdx.x & 31;
    const int sub  = lane / LANES;
    const int li   = lane % LANES;
    const int row  = gw * RPW + sub;
    if (row >= n) return;

    const int s = g_off[row];
    const int e = g_off[row + 1];
    float4 acc = make_float4(0.f, 0.f, 0.f, 0.f);
    for (int p = s; p < e; p++) {
        int   src = g_csr_src[p];
        float nm  = g_csr_norm[p];
        float4 h = *(const float4*)(H + (size_t)src * F + li * 4);
        acc.x = fmaf(nm, h.x, acc.x);
        acc.y = fmaf(nm, h.y, acc.y);
        acc.z = fmaf(nm, h.z, acc.z);
        acc.w = fmaf(nm, h.w, acc.w);
    }
    float4 b = *(const float4*)(bias + li * 4);
    acc.x += b.x; acc.y += b.y; acc.z += b.z; acc.w += b.w;
    if (RELU) {
        acc.x = fmaxf(acc.x, 0.f);
        acc.y = fmaxf(acc.y, 0.f);
        acc.z = fmaxf(acc.z, 0.f);
        acc.w = fmaxf(acc.w, 0.f);
    }
    *(float4*)(OUT + (size_t)row * F + li * 4) = acc;
}

// ---------------- thin wrappers binding __device__ globals ----------------
__global__ void __launch_bounds__(256) k_gemm1(const float* __restrict__ x,
                                               const float* __restrict__ W1, int n) {
    gemm_body<128, 128, 16, 8, 8>(x, W1, g_h1, n, NH, NF);
}
__global__ void k_spmm1(const float* __restrict__ b1, int n) {
    spmm_body<NH, 1, true>(g_h1, b1, g_hr, n);
}
__global__ void __launch_bounds__(128) k_gemm2(const float* __restrict__ W2, int n) {
    gemm_body<128, 64, 16, 8, 8>(g_hr, W2, g_h2, n, NO, NH);
}
__global__ void k_spmm2(const float* __restrict__ b2, float* __restrict__ out, int n) {
    spmm_body<NO, 2, false>(g_h2, b2, out, n);
}

// ---------------- launcher ----------------
extern "C" void kernel_launch(void* const* d_in, const int* in_sizes, int n_in,
                              void* d_out, int out_size) {
    const float* x  = (const float*)d_in[0];
    const int*   ei = (const int*)d_in[1];     // int32 edge_index [2, E]
    const float* W1 = (const float*)d_in[2];
    const float* b1 = (const float*)d_in[3];
    const float* W2 = (const float*)d_in[4];
    const float* b2 = (const float*)d_in[5];
    float* out = (float*)d_out;

    const int n = in_sizes[0] / NF;   // 50000
    const int E = in_sizes[1] / 2;    // 800000
    const int nb = (n + 255) / 256;

    // graph prep
    k_zero_deg<<<(n + 255) / 256, 256>>>();
    k_hist<<<(E + 255) / 256, 256>>>(ei, E, n);
    k_blocksum<<<nb, 256>>>(n);
    k_scan_bases<<<1, 256>>>(nb);
    k_offsets<<<nb, 256>>>(n);
    k_fill<<<(E + 255) / 256, 256>>>(ei, E, n);

    // layer 1: h1 = x @ W1 ; hr = relu(Ahat @ h1 + b1)
    k_gemm1<<<(n + 127) / 128, 256>>>(x, W1, n);
    k_spmm1<<<(n + 7) / 8, 256>>>(b1, n);
    // layer 2: h2 = hr @ W2 ; out = Ahat @ h2 + b2
    k_gemm2<<<(n + 127) / 128, 128>>>(W2, n);
    k_spmm2<<<(n / 2 + 7) / 8, 256>>>(b2, out, n);
}

// round 6
// speedup vs baseline: 1.2828x; 1.1275x over previous
#include <cuda_runtime.h>
#include <cstdint>

// Problem constants (fixed by the dataset)
#define NN   50000
#define EE   800000
#define NF   256
#define NH   128
#define NO   64
#define NB   ((NN + 255) / 256)   // 196 scan blocks

// ---------------- scratch (no allocations allowed) ----------------
__device__ int   g_deg[NN];
__device__ int   g_cursor[NN];
__device__ float g_dis[NN];
__device__ int   g_off[NN + 1];
__device__ int   g_bsum[NB];
__device__ int   g_bbase[NB];
__device__ int   g_csr_src[EE];
__device__ float g_csr_norm[EE];
__device__ float g_h1[(size_t)NN * NH];   // x @ W1
__device__ float g_hr[(size_t)NN * NH];   // relu(agg1 + b1)
__device__ float g_h2[(size_t)NN * NO];   // hr @ W2

// ---------------- packed f32x2 helpers ----------------
__device__ __forceinline__ unsigned long long pack2(float lo, float hi) {
    unsigned long long r;
    asm("mov.b64 %0, {%1, %2};" : "=l"(r) : "f"(lo), "f"(hi));
    return r;
}
__device__ __forceinline__ void unpack2(unsigned long long v, float& lo, float& hi) {
    asm("mov.b64 {%0, %1}, %2;" : "=f"(lo), "=f"(hi) : "l"(v));
}
__device__ __forceinline__ unsigned long long fma2(unsigned long long a,
                                                   unsigned long long b,
                                                   unsigned long long c) {
    unsigned long long d;
    asm("fma.rn.f32x2 %0, %1, %2, %3;" : "=l"(d) : "l"(a), "l"(b), "l"(c));
    return d;
}

// ---------------- small graph-prep kernels ----------------
__global__ void k_zero_deg() {
    int i = blockIdx.x * blockDim.x + threadIdx.x;
    if (i < NN) g_deg[i] = 0;
}

// edge_index is int32
__global__ void k_hist(const int* __restrict__ ei, int E, int n) {
    int e = blockIdx.x * blockDim.x + threadIdx.x;
    if (e < E) {
        int d = ei[E + e];
        if ((unsigned)d < (unsigned)n) atomicAdd(&g_deg[d], 1);
    }
}

__global__ void k_blocksum(int n) {
    __shared__ int sh[256];
    int i = blockIdx.x * 256 + threadIdx.x;
    sh[threadIdx.x] = (i < n) ? g_deg[i] : 0;
    __syncthreads();
    for (int s = 128; s > 0; s >>= 1) {
        if (threadIdx.x < s) sh[threadIdx.x] += sh[threadIdx.x + s];
        __syncthreads();
    }
    if (threadIdx.x == 0) g_bsum[blockIdx.x] = sh[0];
}

// parallel exclusive scan of block sums (nb <= 256), single block
__global__ void k_scan_bases(int nb) {
    __shared__ int sh[256];
    int t = threadIdx.x;
    int v = (t < nb) ? g_bsum[t] : 0;
    sh[t] = v;
    __syncthreads();
    for (int o = 1; o < 256; o <<= 1) {
        int u = (t >= o) ? sh[t - o] : 0;
        __syncthreads();
        sh[t] += u;
        __syncthreads();
    }
    if (t < nb) g_bbase[t] = sh[t] - v;   // exclusive
}

__global__ void k_offsets(int n) {
    __shared__ int sh[256];
    int tid = threadIdx.x;
    int i = blockIdx.x * 256 + tid;
    int v = (i < n) ? g_deg[i] : 0;
    sh[tid] = v;
    __syncthreads();
    for (int ofs = 1; ofs < 256; ofs <<= 1) {
        int t = (tid >= ofs) ? sh[tid - ofs] : 0;
        __syncthreads();
        sh[tid] += t;
        __syncthreads();
    }
    if (i < n) {
        int base = g_bbase[blockIdx.x];
        g_off[i] = base + sh[tid] - v;
        g_dis[i] = (v > 0) ? rsqrtf((float)v) : 0.0f;
        g_cursor[i] = 0;
        if (i == n - 1) g_off[n] = base + sh[tid];
    }
}

__global__ void k_fill(const int* __restrict__ ei, int E, int n) {
    int e = blockIdx.x * blockDim.x + threadIdx.x;
    if (e < E) {
        int s = ei[e];
        int d = ei[E + e];
        if ((unsigned)s < (unsigned)n && (unsigned)d < (unsigned)n) {
            int pos = g_off[d] + atomicAdd(&g_cursor[d], 1);
            g_csr_src[pos]  = s;
            g_csr_norm[pos] = g_dis[s] * g_dis[d];
        }
    }
}

// ---------------- double-buffered register-tiled SGEMM (fma.f32x2) -------------
// C[M,N] = A[M,K] @ B[K,N], row-major, K % BK == 0, N == BN.
template <int BM, int BN, int BK, int TM, int TN>
__device__ __forceinline__ void gemm_body(const float* __restrict__ A,
                                          const float* __restrict__ B,
                                          float* __restrict__ C,
                                          int M, int N, int K) {
    constexpr int NTH = (BM / TM) * (BN / TN);
    constexpr int LA = BM * BK / (4 * NTH);   // float4 A loads per thread
    constexpr int LB = BK * BN / (4 * NTH);   // float4 B loads per thread
    __shared__ __align__(16) float As[2][BK][BM];   // transposed
    __shared__ __align__(16) float Bs[2][BK][BN];

    const int tid = threadIdx.x;
    const int blockRow = blockIdx.x;
    const int tCol = tid % (BN / TN);
    const int tRow = tid / (BN / TN);

    float4 ra[LA], rb[LB];

    auto ldg_tile = [&](int k0) {
#pragma unroll
        for (int t = 0; t < LA; t++) {
            int i = tid + t * NTH;
            int r = i / (BK / 4);
            int kv = i % (BK / 4);
            int gr = blockRow * BM + r;
            ra[t] = (gr < M) ? *(const float4*)(A + (size_t)gr * K + k0 + kv * 4)
                             : make_float4(0.f, 0.f, 0.f, 0.f);
        }
#pragma unroll
        for (int t = 0; t < LB; t++) {
            int i = tid + t * NTH;
            int r = i / (BN / 4);
            int cv = i % (BN / 4);
            rb[t] = *(const float4*)(B + (size_t)(k0 + r) * N + cv * 4);
        }
    };
    auto sts_tile = [&](int buf) {
#pragma unroll
        for (int t = 0; t < LA; t++) {
            int i = tid + t * NTH;
            int r = i / (BK / 4);
            int kv = i % (BK / 4);
            As[buf][kv * 4 + 0][r] = ra[t].x;
            As[buf][kv * 4 + 1][r] = ra[t].y;
            As[buf][kv * 4 + 2][r] = ra[t].z;
            As[buf][kv * 4 + 3][r] = ra[t].w;
        }
#pragma unroll
        for (int t = 0; t < LB; t++) {
            int i = tid + t * NTH;
            int r = i / (BN / 4);
            int cv = i % (BN / 4);
            *(float4*)&Bs[buf][r][cv * 4] = rb[t];
        }
    };

    unsigned long long acc[TM][TN / 2];
#pragma unroll
    for (int i = 0; i < TM; i++)
#pragma unroll
        for (int j = 0; j < TN / 2; j++) acc[i][j] = 0ull;

    const int nk = K / BK;
    ldg_tile(0);
    sts_tile(0);
    __syncthreads();

    for (int kb = 0; kb < nk; kb++) {
        const int cur = kb & 1;
        if (kb + 1 < nk) ldg_tile((kb + 1) * BK);   // overlap with compute below

#pragma unroll
        for (int kk = 0; kk < BK; kk++) {
            float4 a0 = *(const float4*)&As[cur][kk][tRow * TM];
            float4 a1 = *(const float4*)&As[cur][kk][tRow * TM + 4];
            unsigned long long m2[TM];
            m2[0] = pack2(a0.x, a0.x); m2[1] = pack2(a0.y, a0.y);
            m2[2] = pack2(a0.z, a0.z); m2[3] = pack2(a0.w, a0.w);
            m2[4] = pack2(a1.x, a1.x); m2[5] = pack2(a1.y, a1.y);
            m2[6] = pack2(a1.z, a1.z); m2[7] = pack2(a1.w, a1.w);
            unsigned long long b2r[TN / 2];
            const unsigned long long* bp =
                (const unsigned long long*)&Bs[cur][kk][tCol * TN];
#pragma unroll
            for (int j = 0; j < TN / 2; j++) b2r[j] = bp[j];
#pragma unroll
            for (int i = 0; i < TM; i++)
#pragma unroll
                for (int j = 0; j < TN / 2; j++)
                    acc[i][j] = fma2(m2[i], b2r[j], acc[i][j]);
        }

        if (kb + 1 < nk) {
            __syncthreads();
            sts_tile(cur ^ 1);
            __syncthreads();
        }
    }

#pragma unroll
    for (int i = 0; i < TM; i++) {
        int gr = blockRow * BM + tRow * TM + i;
        if (gr >= M) continue;
#pragma unroll
        for (int j = 0; j < TN / 2; j += 2) {
            float a0, a1, a2, a3;
            unpack2(acc[i][j], a0, a1);
            unpack2(acc[i][j + 1], a2, a3);
            *(float4*)(C + (size_t)gr * N + tCol * TN + 2 * j) = make_float4(a0, a1, a2, a3);
        }
    }
}

// ---------------- gather-based SpMM body (CSR rows = dst) ----------------
template <int F, int RPW, bool RELU>
__device__ __forceinline__ void spmm_body(const float* __restrict__ H,
                                          const float* __restrict__ bias,
                                          float* __restrict__ OUT, int n) {
    constexpr int LANES = 32 / RPW;      // F == LANES * 4
    const int gw   = blockIdx.x * (blockDim.x / 32) + (threadIdx.x >> 5);
    const int lane = threadIdx.x & 31;
    const int sub  = lane / LANES;
    const int li   = lane % LANES;
    const int row  = gw * RPW + sub;
    if (row >= n) return;

    const int s = g_off[row];
    const int e = g_off[row + 1];
    float4 acc = make_float4(0.f, 0.f, 0.f, 0.f);
    for (int p = s; p < e; p++) {
        int   src = g_csr_src[p];
        float nm  = g_csr_norm[p];
        float4 h = *(const float4*)(H + (size_t)src * F + li * 4);
        acc.x = fmaf(nm, h.x, acc.x);
        acc.y = fmaf(nm, h.y, acc.y);
        acc.z = fmaf(nm, h.z, acc.z);
        acc.w = fmaf(nm, h.w, acc.w);
    }
    float4 b = *(const float4*)(bias + li * 4);
    acc.x += b.x; acc.y += b.y; acc.z += b.z; acc.w += b.w;
    if (RELU) {
        acc.x = fmaxf(acc.x, 0.f);
        acc.y = fmaxf(acc.y, 0.f);
        acc.z = fmaxf(acc.z, 0.f);
        acc.w = fmaxf(acc.w, 0.f);
    }
    *(float4*)(OUT + (size_t)row * F + li * 4) = acc;
}

// ---------------- thin wrappers binding __device__ globals ----------------
__global__ void __launch_bounds__(256) k_gemm1(const float* __restrict__ x,
                                               const float* __restrict__ W1, int n) {
    gemm_body<128, 128, 16, 8, 8>(x, W1, g_h1, n, NH, NF);
}
__global__ void k_spmm1(const float* __restrict__ b1, int n) {
    spmm_body<NH, 1, true>(g_h1, b1, g_hr, n);
}
__global__ void __launch_bounds__(128) k_gemm2(const float* __restrict__ W2, int n) {
    gemm_body<128, 64, 16, 8, 8>(g_hr, W2, g_h2, n, NO, NH);
}
__global__ void k_spmm2(const float* __restrict__ b2, float* __restrict__ out, int n) {
    spmm_body<NO, 2, false>(g_h2, b2, out, n);
}

// ---------------- launcher ----------------
extern "C" void kernel_launch(void* const* d_in, const int* in_sizes, int n_in,
                              void* d_out, int out_size) {
    const float* x  = (const float*)d_in[0];
    const int*   ei = (const int*)d_in[1];     // int32 edge_index [2, E]
    const float* W1 = (const float*)d_in[2];
    const float* b1 = (const float*)d_in[3];
    const float* W2 = (const float*)d_in[4];
    const float* b2 = (const float*)d_in[5];
    float* out = (float*)d_out;

    const int n = in_sizes[0] / NF;   // 50000
    const int E = in_sizes[1] / 2;    // 800000
    const int nb = (n + 255) / 256;

    // Lazily-created side stream + events (host objects only; created once on
    // the first, non-captured correctness call; reused identically thereafter).
    static cudaStream_t s2 = nullptr;
    static cudaEvent_t evRoot = nullptr, evG = nullptr;
    static bool tried = false;
    if (!tried) {
        tried = true;
        if (cudaStreamCreateWithFlags(&s2, cudaStreamNonBlocking) != cudaSuccess) s2 = nullptr;
        if (s2) {
            if (cudaEventCreateWithFlags(&evRoot, cudaEventDisableTiming) != cudaSuccess ||
                cudaEventCreateWithFlags(&evG,   cudaEventDisableTiming) != cudaSuccess) {
                s2 = nullptr;
            }
        }
    }
    const bool fork = (s2 != nullptr);
    cudaStream_t sg = fork ? s2 : (cudaStream_t)0;

    // ---- fork: GEMM1 (independent of graph prep) on side stream ----
    if (fork) {
        cudaEventRecord(evRoot, 0);
        cudaStreamWaitEvent(s2, evRoot, 0);
    }
    k_gemm1<<<(n + 127) / 128, 256, 0, sg>>>(x, W1, n);
    if (fork) cudaEventRecord(evG, s2);

    // ---- graph prep on main stream (overlaps with GEMM1) ----
    k_zero_deg<<<(n + 255) / 256, 256>>>();
    k_hist<<<(E + 255) / 256, 256>>>(ei, E, n);
    k_blocksum<<<nb, 256>>>(n);
    k_scan_bases<<<1, 256>>>(nb);
    k_offsets<<<nb, 256>>>(n);
    k_fill<<<(E + 255) / 256, 256>>>(ei, E, n);

    // ---- join: SpMM1 needs both h1 and the CSR ----
    if (fork) cudaStreamWaitEvent(0, evG, 0);
    k_spmm1<<<(n + 7) / 8, 256>>>(b1, n);
    // layer 2: h2 = hr @ W2 ; out = Ahat @ h2 + b2
    k_gemm2<<<(n + 127) / 128, 128>>>(W2, n);
    k_spmm2<<<(n / 2 + 7) / 8, 256>>>(b2, out, n);
}